// round 1
// baseline (speedup 1.0000x reference)
#include <cuda_runtime.h>
#include <math.h>

// Problem shape (fixed by the dataset)
#define BB 64
#define SS 4096
#define DXE 512
#define QQ 128
#define DQE 512

#define NSPLIT 8
#define ROWS_PER_SPLIT (SS / NSPLIT)   // 512
#define TPB 256
#define WARPS (TPB / 32)               // 8
#define ROWS_PER_WARP (ROWS_PER_SPLIT / WARPS) // 64

// Scratch (allocation-free: __device__ globals)
__device__ float g_first[BB * DXE];
__device__ float g_pM[BB * NSPLIT];
__device__ float g_pL[BB * NSPLIT];
__device__ float g_pC[BB * NSPLIT * DXE];

// ---------------------------------------------------------------------------
// Kernel A: first[b,:] = (sum_q p[q] * qm[b,q,:]) @ W
// grid = 64, block = 512
// ---------------------------------------------------------------------------
__global__ __launch_bounds__(512) void compute_first_kernel(
    const float* __restrict__ qm,   // [B, Q, DQ]
    const float* __restrict__ W,    // [DQ, DX]
    const float* __restrict__ p)    // [Q, 1]
{
    const int b = blockIdx.x;
    const int t = threadIdx.x;      // 0..511

    __shared__ float sp[QQ];
    __shared__ float sq[DQE];

    if (t < QQ) sp[t] = p[t];
    __syncthreads();

    // new_q[b, t] = sum_q qm[b,q,t] * p[q]
    const float* qb = qm + (size_t)b * QQ * DQE;
    float nq = 0.f;
#pragma unroll 8
    for (int q = 0; q < QQ; q++)
        nq = fmaf(qb[q * DQE + t], sp[q], nq);
    sq[t] = nq;
    __syncthreads();

    // first[b, t] = sum_d sq[d] * W[d, t]
    float f = 0.f;
#pragma unroll 8
    for (int d = 0; d < DQE; d++)
        f = fmaf(sq[d], W[d * DXE + t], f);
    g_first[b * DXE + t] = f;
}

// ---------------------------------------------------------------------------
// Kernel B: fused scores -> online softmax -> weighted sum over a split of S.
// grid = (NSPLIT, B), block = 256 (8 warps). Each warp processes interleaved
// rows, reading each x row exactly once (dot product AND accumulation reuse
// the same registers).
// ---------------------------------------------------------------------------
__global__ __launch_bounds__(TPB) void attn_partial_kernel(
    const float* __restrict__ x)   // [B, S, DX]
{
    const int split = blockIdx.x;
    const int b     = blockIdx.y;
    const int t     = threadIdx.x;
    const int w     = t >> 5;
    const int lane  = t & 31;

    __shared__ float sfirst[DXE];
    __shared__ float sm_m[WARPS];
    __shared__ float sm_l[WARPS];
    __shared__ float4 sm_acc[WARPS][DXE / 4];

    sfirst[t]       = g_first[b * DXE + t];
    sfirst[t + 256] = g_first[b * DXE + t + 256];
    __syncthreads();

    // Per-lane slice of first (as float4, strided by 32 lanes)
    const float4* sf4 = reinterpret_cast<const float4*>(sfirst);
    const float4 f0 = sf4[lane];
    const float4 f1 = sf4[lane + 32];
    const float4 f2 = sf4[lane + 64];
    const float4 f3 = sf4[lane + 96];

    float m = -INFINITY;
    float l = 0.f;
    float4 a0 = make_float4(0.f, 0.f, 0.f, 0.f);
    float4 a1 = a0, a2 = a0, a3 = a0;

    const float4* xb = reinterpret_cast<const float4*>(
        x + (size_t)b * SS * DXE);
    const int s0 = split * ROWS_PER_SPLIT + w;

    for (int r = 0; r < ROWS_PER_WARP; r++) {
        const int s = s0 + WARPS * r;
        const float4* xr = xb + (size_t)s * (DXE / 4);
        // 4 independent LDG.128 per lane -> MLP = 4
        const float4 v0 = xr[lane];
        const float4 v1 = xr[lane + 32];
        const float4 v2 = xr[lane + 64];
        const float4 v3 = xr[lane + 96];

        // dot(first, x_row)
        float d;
        d = v0.x * f0.x;
        d = fmaf(v0.y, f0.y, d); d = fmaf(v0.z, f0.z, d); d = fmaf(v0.w, f0.w, d);
        d = fmaf(v1.x, f1.x, d); d = fmaf(v1.y, f1.y, d); d = fmaf(v1.z, f1.z, d); d = fmaf(v1.w, f1.w, d);
        d = fmaf(v2.x, f2.x, d); d = fmaf(v2.y, f2.y, d); d = fmaf(v2.z, f2.z, d); d = fmaf(v2.w, f2.w, d);
        d = fmaf(v3.x, f3.x, d); d = fmaf(v3.y, f3.y, d); d = fmaf(v3.z, f3.z, d); d = fmaf(v3.w, f3.w, d);
#pragma unroll
        for (int o = 16; o > 0; o >>= 1)
            d += __shfl_xor_sync(0xffffffffu, d, o);

        // online softmax update (d is warp-uniform -> no divergence)
        if (d > m) {
            const float sc = __expf(m - d);  // exp(-inf)=0 handled on first row
            l *= sc;
            a0.x *= sc; a0.y *= sc; a0.z *= sc; a0.w *= sc;
            a1.x *= sc; a1.y *= sc; a1.z *= sc; a1.w *= sc;
            a2.x *= sc; a2.y *= sc; a2.z *= sc; a2.w *= sc;
            a3.x *= sc; a3.y *= sc; a3.z *= sc; a3.w *= sc;
            m = d;
        }
        const float wgt = __expf(d - m);
        l += wgt;
        a0.x = fmaf(wgt, v0.x, a0.x); a0.y = fmaf(wgt, v0.y, a0.y);
        a0.z = fmaf(wgt, v0.z, a0.z); a0.w = fmaf(wgt, v0.w, a0.w);
        a1.x = fmaf(wgt, v1.x, a1.x); a1.y = fmaf(wgt, v1.y, a1.y);
        a1.z = fmaf(wgt, v1.z, a1.z); a1.w = fmaf(wgt, v1.w, a1.w);
        a2.x = fmaf(wgt, v2.x, a2.x); a2.y = fmaf(wgt, v2.y, a2.y);
        a2.z = fmaf(wgt, v2.z, a2.z); a2.w = fmaf(wgt, v2.w, a2.w);
        a3.x = fmaf(wgt, v3.x, a3.x); a3.y = fmaf(wgt, v3.y, a3.y);
        a3.z = fmaf(wgt, v3.z, a3.z); a3.w = fmaf(wgt, v3.w, a3.w);
    }

    // Stash per-warp partials in shared
    if (lane == 0) { sm_m[w] = m; sm_l[w] = l; }
    sm_acc[w][lane]      = a0;
    sm_acc[w][lane + 32] = a1;
    sm_acc[w][lane + 64] = a2;
    sm_acc[w][lane + 96] = a3;
    __syncthreads();

    // Block combine: 8 warps -> one partial (M, L, ctx[512])
    float M = sm_m[0];
#pragma unroll
    for (int i = 1; i < WARPS; i++) M = fmaxf(M, sm_m[i]);

    float ef[WARPS];
    float L = 0.f;
#pragma unroll
    for (int i = 0; i < WARPS; i++) {
        ef[i] = __expf(sm_m[i] - M);
        L = fmaf(ef[i], sm_l[i], L);
    }

    const float* accf = reinterpret_cast<const float*>(sm_acc); // [WARPS][512]
    const int pidx = b * NSPLIT + split;
    float* pc = g_pC + (size_t)pidx * DXE;
#pragma unroll
    for (int half = 0; half < 2; half++) {
        const int d = t + half * 256;
        float c = 0.f;
#pragma unroll
        for (int i = 0; i < WARPS; i++)
            c = fmaf(ef[i], accf[i * DXE + d], c);
        pc[d] = c;
    }
    if (t == 0) { g_pM[pidx] = M; g_pL[pidx] = L; }
}

// ---------------------------------------------------------------------------
// Kernel C: reduce NSPLIT partials per batch -> output [B, DX]
// grid = 64, block = 512
// ---------------------------------------------------------------------------
__global__ __launch_bounds__(512) void attn_reduce_kernel(float* __restrict__ out)
{
    const int b = blockIdx.x;
    const int d = threadIdx.x;

    __shared__ float sM[NSPLIT];
    __shared__ float sL[NSPLIT];
    if (d < NSPLIT) {
        sM[d] = g_pM[b * NSPLIT + d];
        sL[d] = g_pL[b * NSPLIT + d];
    }
    __syncthreads();

    float M = sM[0];
#pragma unroll
    for (int i = 1; i < NSPLIT; i++) M = fmaxf(M, sM[i]);

    float L = 0.f, c = 0.f;
#pragma unroll
    for (int i = 0; i < NSPLIT; i++) {
        const float e = __expf(sM[i] - M);
        L = fmaf(e, sL[i], L);
        c = fmaf(e, g_pC[(size_t)(b * NSPLIT + i) * DXE + d], c);
    }
    out[b * DXE + d] = c / L;
}

// ---------------------------------------------------------------------------
extern "C" void kernel_launch(void* const* d_in, const int* in_sizes, int n_in,
                              void* d_out, int out_size)
{
    const float* x  = (const float*)d_in[0];  // [64, 4096, 512]
    const float* qm = (const float*)d_in[1];  // [64, 128, 512]
    const float* W  = (const float*)d_in[2];  // [512, 512]
    const float* p  = (const float*)d_in[3];  // [128, 1]
    float* out = (float*)d_out;               // [64, 512]

    compute_first_kernel<<<BB, 512>>>(qm, W, p);
    attn_partial_kernel<<<dim3(NSPLIT, BB), TPB>>>(x);
    attn_reduce_kernel<<<BB, 512>>>(out);
}

// round 2
// speedup vs baseline: 1.1891x; 1.1891x over previous
#include <cuda_runtime.h>
#include <math.h>

// Problem shape (fixed by the dataset)
#define BB 64
#define SS 4096
#define DXE 512
#define QQ 128
#define DQE 512

#define NSPLIT 16
#define ROWS_PER_SPLIT (SS / NSPLIT)   // 256
#define TPB 256
#define WARPS (TPB / 32)               // 8
#define ROWS_PER_WARP (ROWS_PER_SPLIT / WARPS) // 32

#define KSPLIT 4
#define KCHUNK (DQE / KSPLIT)          // 128

// Scratch (allocation-free: __device__ globals)
__device__ float g_newq[BB * DQE];
__device__ float g_first_part[KSPLIT][BB * DXE];
__device__ float g_pM[BB * NSPLIT];
__device__ float g_pL[BB * NSPLIT];
__device__ float g_pC[BB * NSPLIT * DXE];

// ---------------------------------------------------------------------------
// Kernel A1: new_q[b,d] = sum_q p[q] * qm[b,q,d]
// One thread per output. grid = 128 CTAs x 256 thr. 16 MB streamed.
// ---------------------------------------------------------------------------
__global__ __launch_bounds__(256) void newq_kernel(
    const float* __restrict__ qm,   // [B, Q, DQ]
    const float* __restrict__ p)    // [Q, 1]
{
    const int idx = blockIdx.x * 256 + threadIdx.x; // 0..32767
    const int b = idx >> 9;
    const int d = idx & 511;

    const float* qb = qm + (size_t)b * QQ * DQE + d;

    float a0 = 0.f, a1 = 0.f, a2 = 0.f, a3 = 0.f;
#pragma unroll 4
    for (int q = 0; q < QQ; q += 4) {
        a0 = fmaf(qb[(q + 0) * DQE], __ldg(&p[q + 0]), a0);
        a1 = fmaf(qb[(q + 1) * DQE], __ldg(&p[q + 1]), a1);
        a2 = fmaf(qb[(q + 2) * DQE], __ldg(&p[q + 2]), a2);
        a3 = fmaf(qb[(q + 3) * DQE], __ldg(&p[q + 3]), a3);
    }
    g_newq[idx] = (a0 + a1) + (a2 + a3);
}

// ---------------------------------------------------------------------------
// Kernel A2: first_part[kc][b,t] = sum_{d in chunk kc} new_q[b,d] * W[d,t]
// grid = (KSPLIT, B) x 512 thr. W stays hot in L2.
// ---------------------------------------------------------------------------
__global__ __launch_bounds__(512) void first_kernel(
    const float* __restrict__ W)    // [DQ, DX]
{
    const int kc = blockIdx.x;
    const int b  = blockIdx.y;
    const int t  = threadIdx.x;

    __shared__ float sq[KCHUNK];
    if (t < KCHUNK) sq[t] = g_newq[b * DQE + kc * KCHUNK + t];
    __syncthreads();

    const float* Wc = W + (size_t)(kc * KCHUNK) * DXE + t;
    float f0 = 0.f, f1 = 0.f;
#pragma unroll 8
    for (int d = 0; d < KCHUNK; d += 2) {
        f0 = fmaf(sq[d + 0], Wc[(d + 0) * DXE], f0);
        f1 = fmaf(sq[d + 1], Wc[(d + 1) * DXE], f1);
    }
    g_first_part[kc][b * DXE + t] = f0 + f1;
}

// ---------------------------------------------------------------------------
// Kernel B: fused scores -> online softmax -> weighted sum over a split of S.
// grid = (NSPLIT, B), block = 256 (8 warps). Reads each x row exactly once.
// ---------------------------------------------------------------------------
__global__ __launch_bounds__(TPB) void attn_partial_kernel(
    const float* __restrict__ x)   // [B, S, DX]
{
    const int split = blockIdx.x;
    const int b     = blockIdx.y;
    const int t     = threadIdx.x;
    const int w     = t >> 5;
    const int lane  = t & 31;

    __shared__ float sfirst[DXE];
    __shared__ float sm_m[WARPS];
    __shared__ float sm_l[WARPS];
    __shared__ float4 sm_acc[WARPS][DXE / 4];

    // sum the 4 split-K partials of `first`
#pragma unroll
    for (int half = 0; half < 2; half++) {
        const int d = t + half * 256;
        float f = 0.f;
#pragma unroll
        for (int kc = 0; kc < KSPLIT; kc++)
            f += g_first_part[kc][b * DXE + d];
        sfirst[d] = f;
    }
    __syncthreads();

    // Per-lane slice of first (as float4, strided by 32 lanes)
    const float4* sf4 = reinterpret_cast<const float4*>(sfirst);
    const float4 f0 = sf4[lane];
    const float4 f1 = sf4[lane + 32];
    const float4 f2 = sf4[lane + 64];
    const float4 f3 = sf4[lane + 96];

    float m = -INFINITY;
    float l = 0.f;
    float4 a0 = make_float4(0.f, 0.f, 0.f, 0.f);
    float4 a1 = a0, a2 = a0, a3 = a0;

    const float4* xb = reinterpret_cast<const float4*>(
        x + (size_t)b * SS * DXE);
    const int s0 = split * ROWS_PER_SPLIT + w;

    for (int r = 0; r < ROWS_PER_WARP; r++) {
        const int s = s0 + WARPS * r;
        const float4* xr = xb + (size_t)s * (DXE / 4);
        // 4 independent LDG.128 per lane -> MLP = 4
        const float4 v0 = xr[lane];
        const float4 v1 = xr[lane + 32];
        const float4 v2 = xr[lane + 64];
        const float4 v3 = xr[lane + 96];

        // dot(first, x_row)
        float d;
        d = v0.x * f0.x;
        d = fmaf(v0.y, f0.y, d); d = fmaf(v0.z, f0.z, d); d = fmaf(v0.w, f0.w, d);
        d = fmaf(v1.x, f1.x, d); d = fmaf(v1.y, f1.y, d); d = fmaf(v1.z, f1.z, d); d = fmaf(v1.w, f1.w, d);
        d = fmaf(v2.x, f2.x, d); d = fmaf(v2.y, f2.y, d); d = fmaf(v2.z, f2.z, d); d = fmaf(v2.w, f2.w, d);
        d = fmaf(v3.x, f3.x, d); d = fmaf(v3.y, f3.y, d); d = fmaf(v3.z, f3.z, d); d = fmaf(v3.w, f3.w, d);
#pragma unroll
        for (int o = 16; o > 0; o >>= 1)
            d += __shfl_xor_sync(0xffffffffu, d, o);

        // online softmax update (d is warp-uniform -> no divergence)
        if (d > m) {
            const float sc = __expf(m - d);  // exp(-inf)=0 handled on first row
            l *= sc;
            a0.x *= sc; a0.y *= sc; a0.z *= sc; a0.w *= sc;
            a1.x *= sc; a1.y *= sc; a1.z *= sc; a1.w *= sc;
            a2.x *= sc; a2.y *= sc; a2.z *= sc; a2.w *= sc;
            a3.x *= sc; a3.y *= sc; a3.z *= sc; a3.w *= sc;
            m = d;
        }
        const float wgt = __expf(d - m);
        l += wgt;
        a0.x = fmaf(wgt, v0.x, a0.x); a0.y = fmaf(wgt, v0.y, a0.y);
        a0.z = fmaf(wgt, v0.z, a0.z); a0.w = fmaf(wgt, v0.w, a0.w);
        a1.x = fmaf(wgt, v1.x, a1.x); a1.y = fmaf(wgt, v1.y, a1.y);
        a1.z = fmaf(wgt, v1.z, a1.z); a1.w = fmaf(wgt, v1.w, a1.w);
        a2.x = fmaf(wgt, v2.x, a2.x); a2.y = fmaf(wgt, v2.y, a2.y);
        a2.z = fmaf(wgt, v2.z, a2.z); a2.w = fmaf(wgt, v2.w, a2.w);
        a3.x = fmaf(wgt, v3.x, a3.x); a3.y = fmaf(wgt, v3.y, a3.y);
        a3.z = fmaf(wgt, v3.z, a3.z); a3.w = fmaf(wgt, v3.w, a3.w);
    }

    // Stash per-warp partials in shared
    if (lane == 0) { sm_m[w] = m; sm_l[w] = l; }
    sm_acc[w][lane]      = a0;
    sm_acc[w][lane + 32] = a1;
    sm_acc[w][lane + 64] = a2;
    sm_acc[w][lane + 96] = a3;
    __syncthreads();

    // Block combine: 8 warps -> one partial (M, L, ctx[512])
    float M = sm_m[0];
#pragma unroll
    for (int i = 1; i < WARPS; i++) M = fmaxf(M, sm_m[i]);

    float ef[WARPS];
    float L = 0.f;
#pragma unroll
    for (int i = 0; i < WARPS; i++) {
        ef[i] = __expf(sm_m[i] - M);
        L = fmaf(ef[i], sm_l[i], L);
    }

    const float* accf = reinterpret_cast<const float*>(sm_acc); // [WARPS][512]
    const int pidx = b * NSPLIT + split;
    float* pc = g_pC + (size_t)pidx * DXE;
#pragma unroll
    for (int half = 0; half < 2; half++) {
        const int d = t + half * 256;
        float c = 0.f;
#pragma unroll
        for (int i = 0; i < WARPS; i++)
            c = fmaf(ef[i], accf[i * DXE + d], c);
        pc[d] = c;
    }
    if (t == 0) { g_pM[pidx] = M; g_pL[pidx] = L; }
}

// ---------------------------------------------------------------------------
// Kernel C: reduce NSPLIT partials per batch -> output [B, DX]
// grid = 64, block = 512
// ---------------------------------------------------------------------------
__global__ __launch_bounds__(512) void attn_reduce_kernel(float* __restrict__ out)
{
    const int b = blockIdx.x;
    const int d = threadIdx.x;

    __shared__ float sM[NSPLIT];
    __shared__ float sL[NSPLIT];
    if (d < NSPLIT) {
        sM[d] = g_pM[b * NSPLIT + d];
        sL[d] = g_pL[b * NSPLIT + d];
    }
    __syncthreads();

    float M = sM[0];
#pragma unroll
    for (int i = 1; i < NSPLIT; i++) M = fmaxf(M, sM[i]);

    float L = 0.f, c = 0.f;
#pragma unroll
    for (int i = 0; i < NSPLIT; i++) {
        const float e = __expf(sM[i] - M);
        L = fmaf(e, sL[i], L);
        c = fmaf(e, g_pC[(size_t)(b * NSPLIT + i) * DXE + d], c);
    }
    out[b * DXE + d] = c / L;
}

// ---------------------------------------------------------------------------
extern "C" void kernel_launch(void* const* d_in, const int* in_sizes, int n_in,
                              void* d_out, int out_size)
{
    const float* x  = (const float*)d_in[0];  // [64, 4096, 512]
    const float* qm = (const float*)d_in[1];  // [64, 128, 512]
    const float* W  = (const float*)d_in[2];  // [512, 512]
    const float* p  = (const float*)d_in[3];  // [128, 1]
    float* out = (float*)d_out;               // [64, 512]

    newq_kernel<<<(BB * DQE) / 256, 256>>>(qm, p);
    first_kernel<<<dim3(KSPLIT, BB), 512>>>(W);
    attn_partial_kernel<<<dim3(NSPLIT, BB), TPB>>>(x);
    attn_reduce_kernel<<<BB, 512>>>(out);
}

// round 3
// speedup vs baseline: 1.2589x; 1.0587x over previous
#include <cuda_runtime.h>
#include <math.h>

// Problem shape (fixed by the dataset)
#define BB 64
#define SS 4096
#define DXE 512
#define QQ 128
#define DQE 512

#define NSPLIT 16
#define ROWS_PER_SPLIT (SS / NSPLIT)   // 256
#define TPB 256
#define WARPS (TPB / 32)               // 8
#define ROWS_PER_WARP (ROWS_PER_SPLIT / WARPS) // 16... (256/8)=32

#define KSPLIT 4
#define KCHUNK (DQE / KSPLIT)          // 128

#define QHALVES 2
#define QH (QQ / QHALVES)              // 64

// Scratch (allocation-free: __device__ globals)
__device__ float g_newq_part[QHALVES][BB * DQE];
__device__ float g_first_part[KSPLIT][BB * DXE];
__device__ float g_pM[BB * NSPLIT];
__device__ float g_pL[BB * NSPLIT];
__device__ float g_pC[BB * NSPLIT * DXE];

// ---------------------------------------------------------------------------
// Kernel A1: new_q partials. newq_part[h][b,d] = sum_{q in half h} p[q]*qm[b,q,d]
// grid = 256 CTAs x 256 thr (one thread per (h,b,d)). MLP=8.
// ---------------------------------------------------------------------------
__global__ __launch_bounds__(256) void newq_kernel(
    const float* __restrict__ qm,   // [B, Q, DQ]
    const float* __restrict__ p)    // [Q, 1]
{
    const int idx = blockIdx.x * 256 + threadIdx.x; // 0..65535
    const int h   = idx >> 15;
    const int rem = idx & 32767;
    const int b   = rem >> 9;
    const int d   = rem & 511;

    const float* qb = qm + (size_t)b * QQ * DQE + (size_t)(h * QH) * DQE + d;
    const float* ph = p + h * QH;

    float a0 = 0.f, a1 = 0.f, a2 = 0.f, a3 = 0.f;
    float a4 = 0.f, a5 = 0.f, a6 = 0.f, a7 = 0.f;
#pragma unroll 8
    for (int q = 0; q < QH; q += 8) {
        a0 = fmaf(qb[(q + 0) * DQE], __ldg(&ph[q + 0]), a0);
        a1 = fmaf(qb[(q + 1) * DQE], __ldg(&ph[q + 1]), a1);
        a2 = fmaf(qb[(q + 2) * DQE], __ldg(&ph[q + 2]), a2);
        a3 = fmaf(qb[(q + 3) * DQE], __ldg(&ph[q + 3]), a3);
        a4 = fmaf(qb[(q + 4) * DQE], __ldg(&ph[q + 4]), a4);
        a5 = fmaf(qb[(q + 5) * DQE], __ldg(&ph[q + 5]), a5);
        a6 = fmaf(qb[(q + 6) * DQE], __ldg(&ph[q + 6]), a6);
        a7 = fmaf(qb[(q + 7) * DQE], __ldg(&ph[q + 7]), a7);
    }
    g_newq_part[h][rem] = ((a0 + a1) + (a2 + a3)) + ((a4 + a5) + (a6 + a7));
}

// ---------------------------------------------------------------------------
// Kernel A2: first_part[kc][b,t] = sum_{d in chunk kc} new_q[b,d] * W[d,t]
// grid = (KSPLIT, B) x 512 thr. W stays hot in L2.
// ---------------------------------------------------------------------------
__global__ __launch_bounds__(512) void first_kernel(
    const float* __restrict__ W)    // [DQ, DX]
{
    const int kc = blockIdx.x;
    const int b  = blockIdx.y;
    const int t  = threadIdx.x;

    __shared__ float sq[KCHUNK];
    if (t < KCHUNK) {
        const int off = b * DQE + kc * KCHUNK + t;
        sq[t] = g_newq_part[0][off] + g_newq_part[1][off];
    }
    __syncthreads();

    const float* Wc = W + (size_t)(kc * KCHUNK) * DXE + t;
    float f0 = 0.f, f1 = 0.f, f2 = 0.f, f3 = 0.f;
#pragma unroll 8
    for (int d = 0; d < KCHUNK; d += 4) {
        f0 = fmaf(sq[d + 0], Wc[(d + 0) * DXE], f0);
        f1 = fmaf(sq[d + 1], Wc[(d + 1) * DXE], f1);
        f2 = fmaf(sq[d + 2], Wc[(d + 2) * DXE], f2);
        f3 = fmaf(sq[d + 3], Wc[(d + 3) * DXE], f3);
    }
    g_first_part[kc][b * DXE + t] = (f0 + f1) + (f2 + f3);
}

// ---------------------------------------------------------------------------
// Kernel B: fused scores -> online softmax -> weighted sum over a split of S.
// grid = (NSPLIT, B), block = 256 (8 warps). Reads each x row exactly once.
// ---------------------------------------------------------------------------
__global__ __launch_bounds__(TPB) void attn_partial_kernel(
    const float* __restrict__ x)   // [B, S, DX]
{
    const int split = blockIdx.x;
    const int b     = blockIdx.y;
    const int t     = threadIdx.x;
    const int w     = t >> 5;
    const int lane  = t & 31;

    __shared__ float sfirst[DXE];
    __shared__ float sm_m[WARPS];
    __shared__ float sm_l[WARPS];
    __shared__ float4 sm_acc[WARPS][DXE / 4];

    // sum the 4 split-K partials of `first`
#pragma unroll
    for (int half = 0; half < 2; half++) {
        const int d = t + half * 256;
        float f = 0.f;
#pragma unroll
        for (int kc = 0; kc < KSPLIT; kc++)
            f += g_first_part[kc][b * DXE + d];
        sfirst[d] = f;
    }
    __syncthreads();

    // Per-lane slice of first (as float4, strided by 32 lanes)
    const float4* sf4 = reinterpret_cast<const float4*>(sfirst);
    const float4 f0 = sf4[lane];
    const float4 f1 = sf4[lane + 32];
    const float4 f2 = sf4[lane + 64];
    const float4 f3 = sf4[lane + 96];

    float m = -INFINITY;
    float l = 0.f;
    float4 a0 = make_float4(0.f, 0.f, 0.f, 0.f);
    float4 a1 = a0, a2 = a0, a3 = a0;

    const float4* xb = reinterpret_cast<const float4*>(
        x + (size_t)b * SS * DXE);
    const int s0 = split * ROWS_PER_SPLIT + w;

    for (int r = 0; r < ROWS_PER_WARP; r++) {
        const int s = s0 + WARPS * r;
        const float4* xr = xb + (size_t)s * (DXE / 4);
        // 4 independent LDG.128 per lane -> MLP = 4
        const float4 v0 = xr[lane];
        const float4 v1 = xr[lane + 32];
        const float4 v2 = xr[lane + 64];
        const float4 v3 = xr[lane + 96];

        // dot(first, x_row)
        float d;
        d = v0.x * f0.x;
        d = fmaf(v0.y, f0.y, d); d = fmaf(v0.z, f0.z, d); d = fmaf(v0.w, f0.w, d);
        d = fmaf(v1.x, f1.x, d); d = fmaf(v1.y, f1.y, d); d = fmaf(v1.z, f1.z, d); d = fmaf(v1.w, f1.w, d);
        d = fmaf(v2.x, f2.x, d); d = fmaf(v2.y, f2.y, d); d = fmaf(v2.z, f2.z, d); d = fmaf(v2.w, f2.w, d);
        d = fmaf(v3.x, f3.x, d); d = fmaf(v3.y, f3.y, d); d = fmaf(v3.z, f3.z, d); d = fmaf(v3.w, f3.w, d);
#pragma unroll
        for (int o = 16; o > 0; o >>= 1)
            d += __shfl_xor_sync(0xffffffffu, d, o);

        // online softmax update (d is warp-uniform -> no divergence)
        if (d > m) {
            const float sc = __expf(m - d);  // exp(-inf)=0 handled on first row
            l *= sc;
            a0.x *= sc; a0.y *= sc; a0.z *= sc; a0.w *= sc;
            a1.x *= sc; a1.y *= sc; a1.z *= sc; a1.w *= sc;
            a2.x *= sc; a2.y *= sc; a2.z *= sc; a2.w *= sc;
            a3.x *= sc; a3.y *= sc; a3.z *= sc; a3.w *= sc;
            m = d;
        }
        const float wgt = __expf(d - m);
        l += wgt;
        a0.x = fmaf(wgt, v0.x, a0.x); a0.y = fmaf(wgt, v0.y, a0.y);
        a0.z = fmaf(wgt, v0.z, a0.z); a0.w = fmaf(wgt, v0.w, a0.w);
        a1.x = fmaf(wgt, v1.x, a1.x); a1.y = fmaf(wgt, v1.y, a1.y);
        a1.z = fmaf(wgt, v1.z, a1.z); a1.w = fmaf(wgt, v1.w, a1.w);
        a2.x = fmaf(wgt, v2.x, a2.x); a2.y = fmaf(wgt, v2.y, a2.y);
        a2.z = fmaf(wgt, v2.z, a2.z); a2.w = fmaf(wgt, v2.w, a2.w);
        a3.x = fmaf(wgt, v3.x, a3.x); a3.y = fmaf(wgt, v3.y, a3.y);
        a3.z = fmaf(wgt, v3.z, a3.z); a3.w = fmaf(wgt, v3.w, a3.w);
    }

    // Stash per-warp partials in shared
    if (lane == 0) { sm_m[w] = m; sm_l[w] = l; }
    sm_acc[w][lane]      = a0;
    sm_acc[w][lane + 32] = a1;
    sm_acc[w][lane + 64] = a2;
    sm_acc[w][lane + 96] = a3;
    __syncthreads();

    // Block combine: 8 warps -> one partial (M, L, ctx[512])
    float M = sm_m[0];
#pragma unroll
    for (int i = 1; i < WARPS; i++) M = fmaxf(M, sm_m[i]);

    float ef[WARPS];
    float L = 0.f;
#pragma unroll
    for (int i = 0; i < WARPS; i++) {
        ef[i] = __expf(sm_m[i] - M);
        L = fmaf(ef[i], sm_l[i], L);
    }

    const float* accf = reinterpret_cast<const float*>(sm_acc); // [WARPS][512]
    const int pidx = b * NSPLIT + split;
    float* pc = g_pC + (size_t)pidx * DXE;
#pragma unroll
    for (int half = 0; half < 2; half++) {
        const int d = t + half * 256;
        float c = 0.f;
#pragma unroll
        for (int i = 0; i < WARPS; i++)
            c = fmaf(ef[i], accf[i * DXE + d], c);
        pc[d] = c;
    }
    if (t == 0) { g_pM[pidx] = M; g_pL[pidx] = L; }
}

// ---------------------------------------------------------------------------
// Kernel C: reduce NSPLIT partials per batch -> output [B, DX]
// grid = (2, B) x 256 thr. All 16 partial loads issued up front (MLP=16).
// ---------------------------------------------------------------------------
__global__ __launch_bounds__(256) void attn_reduce_kernel(float* __restrict__ out)
{
    const int b = blockIdx.y;
    const int d = blockIdx.x * 256 + threadIdx.x;

    __shared__ float sM[NSPLIT];
    __shared__ float sL[NSPLIT];
    if (threadIdx.x < NSPLIT) {
        sM[threadIdx.x] = g_pM[b * NSPLIT + threadIdx.x];
        sL[threadIdx.x] = g_pL[b * NSPLIT + threadIdx.x];
    }

    // Issue all 16 partial-context loads immediately (independent of smem).
    float cvals[NSPLIT];
#pragma unroll
    for (int i = 0; i < NSPLIT; i++)
        cvals[i] = g_pC[(size_t)(b * NSPLIT + i) * DXE + d];

    __syncthreads();

    float M = sM[0];
#pragma unroll
    for (int i = 1; i < NSPLIT; i++) M = fmaxf(M, sM[i]);

    float L = 0.f, c = 0.f;
#pragma unroll
    for (int i = 0; i < NSPLIT; i++) {
        const float e = __expf(sM[i] - M);
        L = fmaf(e, sL[i], L);
        c = fmaf(e, cvals[i], c);
    }
    out[b * DXE + d] = c / L;
}

// ---------------------------------------------------------------------------
extern "C" void kernel_launch(void* const* d_in, const int* in_sizes, int n_in,
                              void* d_out, int out_size)
{
    const float* x  = (const float*)d_in[0];  // [64, 4096, 512]
    const float* qm = (const float*)d_in[1];  // [64, 128, 512]
    const float* W  = (const float*)d_in[2];  // [512, 512]
    const float* p  = (const float*)d_in[3];  // [128, 1]
    float* out = (float*)d_out;               // [64, 512]

    newq_kernel<<<(QHALVES * BB * DQE) / 256, 256>>>(qm, p);
    first_kernel<<<dim3(KSPLIT, BB), 512>>>(W);
    attn_partial_kernel<<<dim3(NSPLIT, BB), TPB>>>(x);
    attn_reduce_kernel<<<dim3(2, BB), 256>>>(out);
}